// round 1
// baseline (speedup 1.0000x reference)
#include <cuda_runtime.h>
#include <math.h>

// Problem dims
constexpr int Bn = 2, Sn = 2048, Hn = 4096, NHn = 32, NKVn = 8, HDn = 128;
constexpr int Mn = Bn * Sn;            // 4096 rows of X
constexpr float QK_SCALE = 0.08838834764831845f; // 1/sqrt(128)

// Scratch (allocation-free: __device__ globals)
__device__ float g_Q[(size_t)Bn * NHn * Sn * HDn];   // [b][h][s][d]  64 MiB
__device__ float g_K[(size_t)Bn * NKVn * Sn * HDn];  // [b][kh][s][d] 16 MiB
__device__ float g_V[(size_t)Bn * NKVn * Sn * HDn];  // 16 MiB
__device__ float g_A[(size_t)Bn * Sn * NHn * HDn];   // [b][s][h*d]   64 MiB

// ---------------------------------------------------------------------------
// SGEMM 128x128 tile, K-step 8, 256 threads, 8x8 per thread (split 4+4 chunks)
// MODE 0: C[m][n] row-major (N cols)
// MODE 1: write to Q layout [b][h][s][d]  (N = NH*HD = 4096)
// MODE 2: write to KV layout [b][kh][s][d] (N = NKV*HD = 1024)
// ---------------------------------------------------------------------------
template <int MODE>
__global__ __launch_bounds__(256) void sgemm_kernel(
    const float* __restrict__ A, const float* __restrict__ Bw,
    float* __restrict__ C, int N, int K)
{
    __shared__ float As[8][128];   // [k][m]
    __shared__ float Bs[8][128];   // [k][n]

    const int tid = threadIdx.x;
    const int m0 = blockIdx.y * 128;
    const int n0 = blockIdx.x * 128;
    const int tr = tid >> 4;       // 0..15
    const int tc = tid & 15;       // 0..15

    float acc[8][8];
#pragma unroll
    for (int i = 0; i < 8; i++)
#pragma unroll
        for (int j = 0; j < 8; j++) acc[i][j] = 0.f;

    const int ar = tid >> 1;             // 0..127
    const int ac4 = (tid & 1) * 4;       // 0 or 4
    const int br = tid >> 5;             // 0..7
    const int bc4 = (tid & 31) * 4;      // 0..124

    const float* Aptr = A + (size_t)(m0 + ar) * K + ac4;
    const float* Bptr = Bw + (size_t)br * N + n0 + bc4;

    for (int kk = 0; kk < K; kk += 8) {
        float4 av = *reinterpret_cast<const float4*>(Aptr + kk);
        float4 bv = *reinterpret_cast<const float4*>(Bptr + (size_t)kk * N);
        __syncthreads();
        As[ac4 + 0][ar] = av.x;
        As[ac4 + 1][ar] = av.y;
        As[ac4 + 2][ar] = av.z;
        As[ac4 + 3][ar] = av.w;
        *reinterpret_cast<float4*>(&Bs[br][bc4]) = bv;
        __syncthreads();

#pragma unroll
        for (int k = 0; k < 8; k++) {
            float4 a0 = *reinterpret_cast<const float4*>(&As[k][tr * 4]);
            float4 a1 = *reinterpret_cast<const float4*>(&As[k][64 + tr * 4]);
            float4 b0 = *reinterpret_cast<const float4*>(&Bs[k][tc * 4]);
            float4 b1 = *reinterpret_cast<const float4*>(&Bs[k][64 + tc * 4]);
            float a[8] = {a0.x, a0.y, a0.z, a0.w, a1.x, a1.y, a1.z, a1.w};
            float b[8] = {b0.x, b0.y, b0.z, b0.w, b1.x, b1.y, b1.z, b1.w};
#pragma unroll
            for (int i = 0; i < 8; i++)
#pragma unroll
                for (int j = 0; j < 8; j++)
                    acc[i][j] = fmaf(a[i], b[j], acc[i][j]);
        }
    }

    // Epilogue
#pragma unroll
    for (int i = 0; i < 8; i++) {
        int r = (i < 4) ? (tr * 4 + i) : (64 + tr * 4 + (i - 4));
        int m = m0 + r;
#pragma unroll
        for (int j = 0; j < 8; j++) {
            int cdx = (j < 4) ? (tc * 4 + j) : (64 + tc * 4 + (j - 4));
            int n = n0 + cdx;
            float v = acc[i][j];
            if (MODE == 0) {
                C[(size_t)m * N + n] = v;
            } else if (MODE == 1) {
                int b = m >> 11, s = m & 2047;
                int h = n >> 7, d = n & 127;
                C[(((size_t)(b * NHn + h) * Sn) + s) * HDn + d] = v;
            } else {
                int b = m >> 11, s = m & 2047;
                int h = n >> 7, d = n & 127;
                C[(((size_t)(b * NKVn + h) * Sn) + s) * HDn + d] = v;
            }
        }
    }
}

// ---------------------------------------------------------------------------
// RoPE (in place, [bh][s][128] layout). One thread per (bh, s, d<64) pair.
// position_ids is a broadcast arange -> pos == s.
// ---------------------------------------------------------------------------
__global__ void rope_kernel(float* __restrict__ X, int total)
{
    int idx = blockIdx.x * 256 + threadIdx.x;
    if (idx >= total) return;
    int d = idx & 63;
    int s = (idx >> 6) & (Sn - 1);
    int bh = idx >> 17;   // 64*2048 = 2^17
    float inv = powf(10000.f, -(float)d / 64.f);
    float ang = (float)s * inv;
    float sn, cs;
    sincosf(ang, &sn, &cs);
    size_t base = ((size_t)bh * Sn + s) * HDn;
    float x0 = X[base + d];
    float x1 = X[base + d + 64];
    X[base + d]      = x0 * cs - x1 * sn;
    X[base + d + 64] = x1 * cs + x0 * sn;
}

// ---------------------------------------------------------------------------
// Flash attention, fp32, BQ=BK=64, 256 threads.
// Thread (tx=tid%16, ty=tid/16): scores 4 rows x 4 cols, output 4 rows x 8 cols
// (cols split tx*4 and 64+tx*4 for conflict-free smem).
// K tile stored transposed [d][k] (stride 68) for conflict-free score loads.
// P tile aliases the K tile region.
// ---------------------------------------------------------------------------
constexpr int BQ = 64, BK = 64, KTP = 68;
constexpr int ATTN_SMEM = (BQ * HDn + HDn * KTP + BK * HDn) * 4; // 100352 B

__global__ __launch_bounds__(256, 2) void attn_kernel()
{
    extern __shared__ float sm[];
    float* Qs = sm;                    // [64][128]
    float* Kt = Qs + BQ * HDn;         // [128][68]  (aliased by Ss)
    float* Vs = Kt + HDn * KTP;        // [64][128]
    float* Ss = Kt;                    // [64][64]

    const int qt = blockIdx.x, h = blockIdx.y, b = blockIdx.z;
    const int tid = threadIdx.x;
    const int tx = tid & 15, ty = tid >> 4;
    const int kvh = h >> 2;            // NH/NKV = 4

    const float* Qg = g_Q + ((size_t)(b * NHn + h) * Sn + qt * BQ) * HDn;
    const float* Kg = g_K + ((size_t)(b * NKVn + kvh) * Sn) * HDn;
    const float* Vg = g_V + ((size_t)(b * NKVn + kvh) * Sn) * HDn;

    for (int i = tid; i < BQ * HDn; i += 256) Qs[i] = Qg[i] * QK_SCALE;

    float acc[4][8];
#pragma unroll
    for (int i = 0; i < 4; i++)
#pragma unroll
        for (int j = 0; j < 8; j++) acc[i][j] = 0.f;
    float mi[4] = {-1e30f, -1e30f, -1e30f, -1e30f};
    float li[4] = {0.f, 0.f, 0.f, 0.f};

    const int nkt = qt + 1;            // causal: only tiles kt <= qt
    for (int kt = 0; kt < nkt; kt++) {
        __syncthreads();   // prev iter's Ss/Vs reads (and initial Qs stores) done
        const float* Ktile = Kg + (size_t)kt * BK * HDn;
        const float* Vtile = Vg + (size_t)kt * BK * HDn;
        for (int i = tid; i < BK * HDn; i += 256) {
            int r = i >> 7, d = i & 127;
            Kt[d * KTP + r] = Ktile[i];
            Vs[i] = Vtile[i];
        }
        __syncthreads();

        // ---- scores: sc[i][j] = Q[row] . K[col] ----
        float sc[4][4];
#pragma unroll
        for (int i = 0; i < 4; i++)
#pragma unroll
            for (int j = 0; j < 4; j++) sc[i][j] = 0.f;

#pragma unroll 4
        for (int d = 0; d < HDn; d++) {
            float4 kv = *reinterpret_cast<const float4*>(&Kt[d * KTP + tx * 4]);
            float q0 = Qs[(ty * 4 + 0) * HDn + d];
            float q1 = Qs[(ty * 4 + 1) * HDn + d];
            float q2 = Qs[(ty * 4 + 2) * HDn + d];
            float q3 = Qs[(ty * 4 + 3) * HDn + d];
            sc[0][0] = fmaf(q0, kv.x, sc[0][0]); sc[0][1] = fmaf(q0, kv.y, sc[0][1]);
            sc[0][2] = fmaf(q0, kv.z, sc[0][2]); sc[0][3] = fmaf(q0, kv.w, sc[0][3]);
            sc[1][0] = fmaf(q1, kv.x, sc[1][0]); sc[1][1] = fmaf(q1, kv.y, sc[1][1]);
            sc[1][2] = fmaf(q1, kv.z, sc[1][2]); sc[1][3] = fmaf(q1, kv.w, sc[1][3]);
            sc[2][0] = fmaf(q2, kv.x, sc[2][0]); sc[2][1] = fmaf(q2, kv.y, sc[2][1]);
            sc[2][2] = fmaf(q2, kv.z, sc[2][2]); sc[2][3] = fmaf(q2, kv.w, sc[2][3]);
            sc[3][0] = fmaf(q3, kv.x, sc[3][0]); sc[3][1] = fmaf(q3, kv.y, sc[3][1]);
            sc[3][2] = fmaf(q3, kv.z, sc[3][2]); sc[3][3] = fmaf(q3, kv.w, sc[3][3]);
        }

        // ---- causal mask (only on the diagonal tile) ----
        if (kt == qt) {
            int qg0 = qt * BQ + ty * 4;
            int kg0 = kt * BK + tx * 4;
#pragma unroll
            for (int i = 0; i < 4; i++)
#pragma unroll
                for (int j = 0; j < 4; j++)
                    if (kg0 + j > qg0 + i) sc[i][j] = -1e30f;
        }

        // ---- online softmax (reduce across tx = 16-lane groups) ----
#pragma unroll
        for (int i = 0; i < 4; i++) {
            float tm = fmaxf(fmaxf(sc[i][0], sc[i][1]), fmaxf(sc[i][2], sc[i][3]));
#pragma unroll
            for (int o = 8; o >= 1; o >>= 1)
                tm = fmaxf(tm, __shfl_xor_sync(0xffffffffu, tm, o));
            float mnew = fmaxf(mi[i], tm);
            float corr = __expf(mi[i] - mnew);
            mi[i] = mnew;
            li[i] *= corr;
#pragma unroll
            for (int j = 0; j < 8; j++) acc[i][j] *= corr;
            float rs = 0.f;
#pragma unroll
            for (int j = 0; j < 4; j++) {
                sc[i][j] = __expf(sc[i][j] - mnew);
                rs += sc[i][j];
            }
#pragma unroll
            for (int o = 8; o >= 1; o >>= 1)
                rs += __shfl_xor_sync(0xffffffffu, rs, o);
            li[i] += rs;
        }

        __syncthreads();   // all Kt reads complete before overwriting with P
#pragma unroll
        for (int i = 0; i < 4; i++)
#pragma unroll
            for (int j = 0; j < 4; j++)
                Ss[(ty * 4 + i) * BK + tx * 4 + j] = sc[i][j];
        __syncthreads();

        // ---- O += P @ V ----
#pragma unroll 2
        for (int k = 0; k < BK; k++) {
            float4 v0 = *reinterpret_cast<const float4*>(&Vs[k * HDn + tx * 4]);
            float4 v1 = *reinterpret_cast<const float4*>(&Vs[k * HDn + 64 + tx * 4]);
            float p0 = Ss[(ty * 4 + 0) * BK + k];
            float p1 = Ss[(ty * 4 + 1) * BK + k];
            float p2 = Ss[(ty * 4 + 2) * BK + k];
            float p3 = Ss[(ty * 4 + 3) * BK + k];
            acc[0][0] = fmaf(p0, v0.x, acc[0][0]); acc[0][1] = fmaf(p0, v0.y, acc[0][1]);
            acc[0][2] = fmaf(p0, v0.z, acc[0][2]); acc[0][3] = fmaf(p0, v0.w, acc[0][3]);
            acc[0][4] = fmaf(p0, v1.x, acc[0][4]); acc[0][5] = fmaf(p0, v1.y, acc[0][5]);
            acc[0][6] = fmaf(p0, v1.z, acc[0][6]); acc[0][7] = fmaf(p0, v1.w, acc[0][7]);
            acc[1][0] = fmaf(p1, v0.x, acc[1][0]); acc[1][1] = fmaf(p1, v0.y, acc[1][1]);
            acc[1][2] = fmaf(p1, v0.z, acc[1][2]); acc[1][3] = fmaf(p1, v0.w, acc[1][3]);
            acc[1][4] = fmaf(p1, v1.x, acc[1][4]); acc[1][5] = fmaf(p1, v1.y, acc[1][5]);
            acc[1][6] = fmaf(p1, v1.z, acc[1][6]); acc[1][7] = fmaf(p1, v1.w, acc[1][7]);
            acc[2][0] = fmaf(p2, v0.x, acc[2][0]); acc[2][1] = fmaf(p2, v0.y, acc[2][1]);
            acc[2][2] = fmaf(p2, v0.z, acc[2][2]); acc[2][3] = fmaf(p2, v0.w, acc[2][3]);
            acc[2][4] = fmaf(p2, v1.x, acc[2][4]); acc[2][5] = fmaf(p2, v1.y, acc[2][5]);
            acc[2][6] = fmaf(p2, v1.z, acc[2][6]); acc[2][7] = fmaf(p2, v1.w, acc[2][7]);
            acc[3][0] = fmaf(p3, v0.x, acc[3][0]); acc[3][1] = fmaf(p3, v0.y, acc[3][1]);
            acc[3][2] = fmaf(p3, v0.z, acc[3][2]); acc[3][3] = fmaf(p3, v0.w, acc[3][3]);
            acc[3][4] = fmaf(p3, v1.x, acc[3][4]); acc[3][5] = fmaf(p3, v1.y, acc[3][5]);
            acc[3][6] = fmaf(p3, v1.z, acc[3][6]); acc[3][7] = fmaf(p3, v1.w, acc[3][7]);
        }
    }

    // write to g_A in [b][s][h*128+d] layout
    float* Og = g_A + ((size_t)(b * Sn + qt * BQ)) * (NHn * HDn) + h * HDn;
#pragma unroll
    for (int i = 0; i < 4; i++) {
        int r = ty * 4 + i;
        float inv = 1.f / li[i];
        float* row = Og + (size_t)r * (NHn * HDn);
#pragma unroll
        for (int j = 0; j < 4; j++) {
            row[tx * 4 + j] = acc[i][j] * inv;
            row[64 + tx * 4 + j] = acc[i][4 + j] * inv;
        }
    }
}

// ---------------------------------------------------------------------------
extern "C" void kernel_launch(void* const* d_in, const int* in_sizes, int n_in,
                              void* d_out, int out_size)
{
    const float* hidden = (const float*)d_in[0];
    // d_in[1] = position_ids (broadcast arange; pos == s, derived in-kernel)
    const float* Wq = (const float*)d_in[2];
    const float* Wk = (const float*)d_in[3];
    const float* Wv = (const float*)d_in[4];
    const float* Wo = (const float*)d_in[5];
    float* out = (float*)d_out;

    float *pQ, *pK, *pV, *pA;
    cudaGetSymbolAddress((void**)&pQ, g_Q);
    cudaGetSymbolAddress((void**)&pK, g_K);
    cudaGetSymbolAddress((void**)&pV, g_V);
    cudaGetSymbolAddress((void**)&pA, g_A);
    cudaFuncSetAttribute(attn_kernel,
                         cudaFuncAttributeMaxDynamicSharedMemorySize, ATTN_SMEM);

    // 1) projections (fused layout transform)
    dim3 gq(NHn * HDn / 128, Mn / 128);     // 32 x 32
    dim3 gkv(NKVn * HDn / 128, Mn / 128);   // 8 x 32
    sgemm_kernel<1><<<gq, 256>>>(hidden, Wq, pQ, NHn * HDn, Hn);
    sgemm_kernel<2><<<gkv, 256>>>(hidden, Wk, pK, NKVn * HDn, Hn);
    sgemm_kernel<2><<<gkv, 256>>>(hidden, Wv, pV, NKVn * HDn, Hn);

    // 2) RoPE on Q and K
    int totQ = Bn * NHn * Sn * 64;
    int totK = Bn * NKVn * Sn * 64;
    rope_kernel<<<totQ / 256, 256>>>(pQ, totQ);
    rope_kernel<<<totK / 256, 256>>>(pK, totK);

    // 3) causal flash attention
    dim3 ga(Sn / BQ, NHn, Bn);              // 32 x 32 x 2
    attn_kernel<<<ga, 256, ATTN_SMEM>>>();

    // 4) output projection
    dim3 go(Hn / 128, Mn / 128);            // 32 x 32
    sgemm_kernel<0><<<go, 256>>>(pA, Wo, out, Hn, Hn);
}

// round 2
// speedup vs baseline: 1.1321x; 1.1321x over previous
#include <cuda_runtime.h>
#include <math.h>

// Problem dims
constexpr int Bn = 2, Sn = 2048, Hn = 4096, NHn = 32, NKVn = 8, HDn = 128;
constexpr int Mn = Bn * Sn;            // 4096 rows of X
constexpr float QK_SCALE = 0.08838834764831845f; // 1/sqrt(128)

// Scratch (allocation-free: __device__ globals)
__device__ float g_Q[(size_t)Bn * NHn * Sn * HDn];   // [b][h][s][d]  64 MiB
__device__ float g_K[(size_t)Bn * NKVn * Sn * HDn];  // [b][kh][s][d] 16 MiB
__device__ float g_V[(size_t)Bn * NKVn * Sn * HDn];  // 16 MiB
__device__ float g_A[(size_t)Bn * Sn * NHn * HDn];   // [b][s][h*d]   64 MiB

// ---------------------------------------------------------------------------
// tf32 tensor-core GEMM: C[M,N] = A[M,K] * B[K,N], 128x128 block, 256 thr.
// 8 warps as 2x4 -> warp tile 64x32. K-step 16 (2x m16n8k8). Smem ping-pong.
// MODE 0: C row-major; MODE 1: Q layout [b][h][s][d]; MODE 2: KV layout.
// ---------------------------------------------------------------------------
#define CVT_TF32(u, f) asm("cvt.rna.tf32.f32 %0, %1;" : "=r"(u) : "f"(f))

template <int MODE>
__global__ __launch_bounds__(256, 1) void tgemm_kernel(
    const float* __restrict__ A, const float* __restrict__ Bw,
    float* __restrict__ C, int N, int K)
{
    // padded strides chosen for conflict-free fragment loads:
    //  As[m][20]: bank = 20*g + t4  -> 32 distinct
    //  Bs[k][136]: bank = 8*t4 + g  -> 32 distinct
    __shared__ float As[2][128][20];
    __shared__ float Bs[2][16][136];

    const int tid = threadIdx.x;
    const int wid = tid >> 5, lane = tid & 31;
    const int g = lane >> 2, t4 = lane & 3;
    const int wr = wid >> 2, wc = wid & 3;     // 2 x 4 warp grid
    const int m0 = blockIdx.y * 128, n0 = blockIdx.x * 128;
    const int wm = wr * 64, wn = wc * 32;

    float c[4][4][4];
#pragma unroll
    for (int mi = 0; mi < 4; mi++)
#pragma unroll
        for (int ni = 0; ni < 4; ni++)
#pragma unroll
            for (int r = 0; r < 4; r++) c[mi][ni][r] = 0.f;

    // global->reg staging mapping
    // A tile 128x16: float4 f in [0,512): m=f>>2, c4=(f&3)*4 ; f = tid, tid+256
    // B tile 16x128: float4 f in [0,512): r=f>>5, c4=(f&31)*4
    const int am0 = tid >> 2, ac0 = (tid & 3) * 4;
    const int am1 = (tid + 256) >> 2, ac1 = ((tid + 256) & 3) * 4;
    const int br0 = tid >> 5, bc0 = (tid & 31) * 4;
    const int br1 = (tid + 256) >> 5, bc1 = ((tid + 256) & 31) * 4;

    const int niter = K / 16;

    float4 ar0, ar1, brg0, brg1;
    // preload tile 0
    ar0 = *reinterpret_cast<const float4*>(&A[(size_t)(m0 + am0) * K + ac0]);
    ar1 = *reinterpret_cast<const float4*>(&A[(size_t)(m0 + am1) * K + ac1]);
    brg0 = *reinterpret_cast<const float4*>(&Bw[(size_t)br0 * N + n0 + bc0]);
    brg1 = *reinterpret_cast<const float4*>(&Bw[(size_t)br1 * N + n0 + bc1]);
    *reinterpret_cast<float4*>(&As[0][am0][ac0]) = ar0;
    *reinterpret_cast<float4*>(&As[0][am1][ac1]) = ar1;
    *reinterpret_cast<float4*>(&Bs[0][br0][bc0]) = brg0;
    *reinterpret_cast<float4*>(&Bs[0][br1][bc1]) = brg1;
    __syncthreads();

    int cur = 0;
    for (int it = 0; it < niter; it++) {
        const bool has_next = (it + 1) < niter;
        if (has_next) {
            const int k0 = (it + 1) * 16;
            ar0 = *reinterpret_cast<const float4*>(&A[(size_t)(m0 + am0) * K + k0 + ac0]);
            ar1 = *reinterpret_cast<const float4*>(&A[(size_t)(m0 + am1) * K + k0 + ac1]);
            brg0 = *reinterpret_cast<const float4*>(&Bw[(size_t)(k0 + br0) * N + n0 + bc0]);
            brg1 = *reinterpret_cast<const float4*>(&Bw[(size_t)(k0 + br1) * N + n0 + bc1]);
        }

        // compute 2 x k8 from smem[cur]
#pragma unroll
        for (int kk = 0; kk < 16; kk += 8) {
            unsigned au[4][4], bu[4][2];
#pragma unroll
            for (int mi = 0; mi < 4; mi++) {
                const int r = wm + mi * 16 + g;
                CVT_TF32(au[mi][0], As[cur][r][kk + t4]);
                CVT_TF32(au[mi][1], As[cur][r + 8][kk + t4]);
                CVT_TF32(au[mi][2], As[cur][r][kk + t4 + 4]);
                CVT_TF32(au[mi][3], As[cur][r + 8][kk + t4 + 4]);
            }
#pragma unroll
            for (int ni = 0; ni < 4; ni++) {
                const int cc = wn + ni * 8 + g;
                CVT_TF32(bu[ni][0], Bs[cur][kk + t4][cc]);
                CVT_TF32(bu[ni][1], Bs[cur][kk + t4 + 4][cc]);
            }
#pragma unroll
            for (int mi = 0; mi < 4; mi++)
#pragma unroll
                for (int ni = 0; ni < 4; ni++) {
                    asm volatile(
                        "mma.sync.aligned.m16n8k8.row.col.f32.tf32.tf32.f32 "
                        "{%0,%1,%2,%3}, {%4,%5,%6,%7}, {%8,%9}, {%0,%1,%2,%3};"
                        : "+f"(c[mi][ni][0]), "+f"(c[mi][ni][1]),
                          "+f"(c[mi][ni][2]), "+f"(c[mi][ni][3])
                        : "r"(au[mi][0]), "r"(au[mi][1]), "r"(au[mi][2]), "r"(au[mi][3]),
                          "r"(bu[ni][0]), "r"(bu[ni][1]));
                }
        }

        if (has_next) {
            const int nxt = cur ^ 1;
            *reinterpret_cast<float4*>(&As[nxt][am0][ac0]) = ar0;
            *reinterpret_cast<float4*>(&As[nxt][am1][ac1]) = ar1;
            *reinterpret_cast<float4*>(&Bs[nxt][br0][bc0]) = brg0;
            *reinterpret_cast<float4*>(&Bs[nxt][br1][bc1]) = brg1;
            __syncthreads();
            cur = nxt;
        }
    }

    // Epilogue: c0:(g,2t4) c1:(g,2t4+1) c2:(g+8,2t4) c3:(g+8,2t4+1)
#pragma unroll
    for (int mi = 0; mi < 4; mi++) {
#pragma unroll
        for (int ni = 0; ni < 4; ni++) {
            const int row0 = m0 + wm + mi * 16 + g;
            const int col = n0 + wn + ni * 8 + 2 * t4;
#pragma unroll
            for (int half = 0; half < 2; half++) {
                const int m = row0 + half * 8;
                float2 v = half ? make_float2(c[mi][ni][2], c[mi][ni][3])
                                : make_float2(c[mi][ni][0], c[mi][ni][1]);
                if (MODE == 0) {
                    *reinterpret_cast<float2*>(&C[(size_t)m * N + col]) = v;
                } else if (MODE == 1) {
                    int b = m >> 11, s = m & 2047;
                    int h = col >> 7, d = col & 127;
                    *reinterpret_cast<float2*>(
                        &C[(((size_t)(b * NHn + h) * Sn) + s) * HDn + d]) = v;
                } else {
                    int b = m >> 11, s = m & 2047;
                    int h = col >> 7, d = col & 127;
                    *reinterpret_cast<float2*>(
                        &C[(((size_t)(b * NKVn + h) * Sn) + s) * HDn + d]) = v;
                }
            }
        }
    }
}

// ---------------------------------------------------------------------------
// RoPE (in place, [bh][s][128] layout). pos == s (position_ids is arange).
// ---------------------------------------------------------------------------
__global__ void rope_kernel(float* __restrict__ X, int total)
{
    int idx = blockIdx.x * 256 + threadIdx.x;
    if (idx >= total) return;
    int d = idx & 63;
    int s = (idx >> 6) & (Sn - 1);
    int bh = idx >> 17;
    float inv = powf(10000.f, -(float)d / 64.f);
    float ang = (float)s * inv;
    float sn, cs;
    sincosf(ang, &sn, &cs);
    size_t base = ((size_t)bh * Sn + s) * HDn;
    float x0 = X[base + d];
    float x1 = X[base + d + 64];
    X[base + d]      = x0 * cs - x1 * sn;
    X[base + d + 64] = x1 * cs + x0 * sn;
}

// ---------------------------------------------------------------------------
// Flash attention, fp32, BQ=BK=64, 256 threads (unchanged from round 1).
// ---------------------------------------------------------------------------
constexpr int BQ = 64, BK = 64, KTP = 68;
constexpr int ATTN_SMEM = (BQ * HDn + HDn * KTP + BK * HDn) * 4; // 100352 B

__global__ __launch_bounds__(256, 2) void attn_kernel()
{
    extern __shared__ float sm[];
    float* Qs = sm;                    // [64][128]
    float* Kt = Qs + BQ * HDn;         // [128][68]  (aliased by Ss)
    float* Vs = Kt + HDn * KTP;        // [64][128]
    float* Ss = Kt;                    // [64][64]

    const int qt = blockIdx.x, h = blockIdx.y, b = blockIdx.z;
    const int tid = threadIdx.x;
    const int tx = tid & 15, ty = tid >> 4;
    const int kvh = h >> 2;

    const float* Qg = g_Q + ((size_t)(b * NHn + h) * Sn + qt * BQ) * HDn;
    const float* Kg = g_K + ((size_t)(b * NKVn + kvh) * Sn) * HDn;
    const float* Vg = g_V + ((size_t)(b * NKVn + kvh) * Sn) * HDn;

    for (int i = tid; i < BQ * HDn; i += 256) Qs[i] = Qg[i] * QK_SCALE;

    float acc[4][8];
#pragma unroll
    for (int i = 0; i < 4; i++)
#pragma unroll
        for (int j = 0; j < 8; j++) acc[i][j] = 0.f;
    float mi[4] = {-1e30f, -1e30f, -1e30f, -1e30f};
    float li[4] = {0.f, 0.f, 0.f, 0.f};

    const int nkt = qt + 1;
    for (int kt = 0; kt < nkt; kt++) {
        __syncthreads();
        const float* Ktile = Kg + (size_t)kt * BK * HDn;
        const float* Vtile = Vg + (size_t)kt * BK * HDn;
        for (int i = tid; i < BK * HDn; i += 256) {
            int r = i >> 7, d = i & 127;
            Kt[d * KTP + r] = Ktile[i];
            Vs[i] = Vtile[i];
        }
        __syncthreads();

        float sc[4][4];
#pragma unroll
        for (int i = 0; i < 4; i++)
#pragma unroll
            for (int j = 0; j < 4; j++) sc[i][j] = 0.f;

#pragma unroll 4
        for (int d = 0; d < HDn; d++) {
            float4 kv = *reinterpret_cast<const float4*>(&Kt[d * KTP + tx * 4]);
            float q0 = Qs[(ty * 4 + 0) * HDn + d];
            float q1 = Qs[(ty * 4 + 1) * HDn + d];
            float q2 = Qs[(ty * 4 + 2) * HDn + d];
            float q3 = Qs[(ty * 4 + 3) * HDn + d];
            sc[0][0] = fmaf(q0, kv.x, sc[0][0]); sc[0][1] = fmaf(q0, kv.y, sc[0][1]);
            sc[0][2] = fmaf(q0, kv.z, sc[0][2]); sc[0][3] = fmaf(q0, kv.w, sc[0][3]);
            sc[1][0] = fmaf(q1, kv.x, sc[1][0]); sc[1][1] = fmaf(q1, kv.y, sc[1][1]);
            sc[1][2] = fmaf(q1, kv.z, sc[1][2]); sc[1][3] = fmaf(q1, kv.w, sc[1][3]);
            sc[2][0] = fmaf(q2, kv.x, sc[2][0]); sc[2][1] = fmaf(q2, kv.y, sc[2][1]);
            sc[2][2] = fmaf(q2, kv.z, sc[2][2]); sc[2][3] = fmaf(q2, kv.w, sc[2][3]);
            sc[3][0] = fmaf(q3, kv.x, sc[3][0]); sc[3][1] = fmaf(q3, kv.y, sc[3][1]);
            sc[3][2] = fmaf(q3, kv.z, sc[3][2]); sc[3][3] = fmaf(q3, kv.w, sc[3][3]);
        }

        if (kt == qt) {
            int qg0 = qt * BQ + ty * 4;
            int kg0 = kt * BK + tx * 4;
#pragma unroll
            for (int i = 0; i < 4; i++)
#pragma unroll
                for (int j = 0; j < 4; j++)
                    if (kg0 + j > qg0 + i) sc[i][j] = -1e30f;
        }

#pragma unroll
        for (int i = 0; i < 4; i++) {
            float tm = fmaxf(fmaxf(sc[i][0], sc[i][1]), fmaxf(sc[i][2], sc[i][3]));
#pragma unroll
            for (int o = 8; o >= 1; o >>= 1)
                tm = fmaxf(tm, __shfl_xor_sync(0xffffffffu, tm, o));
            float mnew = fmaxf(mi[i], tm);
            float corr = __expf(mi[i] - mnew);
            mi[i] = mnew;
            li[i] *= corr;
#pragma unroll
            for (int j = 0; j < 8; j++) acc[i][j] *= corr;
            float rs = 0.f;
#pragma unroll
            for (int j = 0; j < 4; j++) {
                sc[i][j] = __expf(sc[i][j] - mnew);
                rs += sc[i][j];
            }
#pragma unroll
            for (int o = 8; o >= 1; o >>= 1)
                rs += __shfl_xor_sync(0xffffffffu, rs, o);
            li[i] += rs;
        }

        __syncthreads();
#pragma unroll
        for (int i = 0; i < 4; i++)
#pragma unroll
            for (int j = 0; j < 4; j++)
                Ss[(ty * 4 + i) * BK + tx * 4 + j] = sc[i][j];
        __syncthreads();

#pragma unroll 2
        for (int k = 0; k < BK; k++) {
            float4 v0 = *reinterpret_cast<const float4*>(&Vs[k * HDn + tx * 4]);
            float4 v1 = *reinterpret_cast<const float4*>(&Vs[k * HDn + 64 + tx * 4]);
            float p0 = Ss[(ty * 4 + 0) * BK + k];
            float p1 = Ss[(ty * 4 + 1) * BK + k];
            float p2 = Ss[(ty * 4 + 2) * BK + k];
            float p3 = Ss[(ty * 4 + 3) * BK + k];
            acc[0][0] = fmaf(p0, v0.x, acc[0][0]); acc[0][1] = fmaf(p0, v0.y, acc[0][1]);
            acc[0][2] = fmaf(p0, v0.z, acc[0][2]); acc[0][3] = fmaf(p0, v0.w, acc[0][3]);
            acc[0][4] = fmaf(p0, v1.x, acc[0][4]); acc[0][5] = fmaf(p0, v1.y, acc[0][5]);
            acc[0][6] = fmaf(p0, v1.z, acc[0][6]); acc[0][7] = fmaf(p0, v1.w, acc[0][7]);
            acc[1][0] = fmaf(p1, v0.x, acc[1][0]); acc[1][1] = fmaf(p1, v0.y, acc[1][1]);
            acc[1][2] = fmaf(p1, v0.z, acc[1][2]); acc[1][3] = fmaf(p1, v0.w, acc[1][3]);
            acc[1][4] = fmaf(p1, v1.x, acc[1][4]); acc[1][5] = fmaf(p1, v1.y, acc[1][5]);
            acc[1][6] = fmaf(p1, v1.z, acc[1][6]); acc[1][7] = fmaf(p1, v1.w, acc[1][7]);
            acc[2][0] = fmaf(p2, v0.x, acc[2][0]); acc[2][1] = fmaf(p2, v0.y, acc[2][1]);
            acc[2][2] = fmaf(p2, v0.z, acc[2][2]); acc[2][3] = fmaf(p2, v0.w, acc[2][3]);
            acc[2][4] = fmaf(p2, v1.x, acc[2][4]); acc[2][5] = fmaf(p2, v1.y, acc[2][5]);
            acc[2][6] = fmaf(p2, v1.z, acc[2][6]); acc[2][7] = fmaf(p2, v1.w, acc[2][7]);
            acc[3][0] = fmaf(p3, v0.x, acc[3][0]); acc[3][1] = fmaf(p3, v0.y, acc[3][1]);
            acc[3][2] = fmaf(p3, v0.z, acc[3][2]); acc[3][3] = fmaf(p3, v0.w, acc[3][3]);
            acc[3][4] = fmaf(p3, v1.x, acc[3][4]); acc[3][5] = fmaf(p3, v1.y, acc[3][5]);
            acc[3][6] = fmaf(p3, v1.z, acc[3][6]); acc[3][7] = fmaf(p3, v1.w, acc[3][7]);
        }
    }

    float* Og = g_A + ((size_t)(b * Sn + qt * BQ)) * (NHn * HDn) + h * HDn;
#pragma unroll
    for (int i = 0; i < 4; i++) {
        int r = ty * 4 + i;
        float inv = 1.f / li[i];
        float* row = Og + (size_t)r * (NHn * HDn);
#pragma unroll
        for (int j = 0; j < 4; j++) {
            row[tx * 4 + j] = acc[i][j] * inv;
            row[64 + tx * 4 + j] = acc[i][4 + j] * inv;
        }
    }
}

// ---------------------------------------------------------------------------
extern "C" void kernel_launch(void* const* d_in, const int* in_sizes, int n_in,
                              void* d_out, int out_size)
{
    const float* hidden = (const float*)d_in[0];
    // d_in[1] = position_ids (broadcast arange; pos == s, derived in-kernel)
    const float* Wq = (const float*)d_in[2];
    const float* Wk = (const float*)d_in[3];
    const float* Wv = (const float*)d_in[4];
    const float* Wo = (const float*)d_in[5];
    float* out = (float*)d_out;

    float *pQ, *pK, *pV, *pA;
    cudaGetSymbolAddress((void**)&pQ, g_Q);
    cudaGetSymbolAddress((void**)&pK, g_K);
    cudaGetSymbolAddress((void**)&pV, g_V);
    cudaGetSymbolAddress((void**)&pA, g_A);
    cudaFuncSetAttribute(attn_kernel,
                         cudaFuncAttributeMaxDynamicSharedMemorySize, ATTN_SMEM);

    // 1) projections (tf32 tensor cores, fused layout transform)
    dim3 gq(NHn * HDn / 128, Mn / 128);     // 32 x 32
    dim3 gkv(NKVn * HDn / 128, Mn / 128);   // 8 x 32
    tgemm_kernel<1><<<gq, 256>>>(hidden, Wq, pQ, NHn * HDn, Hn);
    tgemm_kernel<2><<<gkv, 256>>>(hidden, Wk, pK, NKVn * HDn, Hn);
    tgemm_kernel<2><<<gkv, 256>>>(hidden, Wv, pV, NKVn * HDn, Hn);

    // 2) RoPE on Q and K
    int totQ = Bn * NHn * Sn * 64;
    int totK = Bn * NKVn * Sn * 64;
    rope_kernel<<<totQ / 256, 256>>>(pQ, totQ);
    rope_kernel<<<totK / 256, 256>>>(pK, totK);

    // 3) causal flash attention (fp32 SIMT, unchanged)
    dim3 ga(Sn / BQ, NHn, Bn);              // 32 x 32 x 2
    attn_kernel<<<ga, 256, ATTN_SMEM>>>();

    // 4) output projection
    dim3 go(Hn / 128, Mn / 128);            // 32 x 32
    tgemm_kernel<0><<<go, 256>>>(pA, Wo, out, Hn, Hn);
}

// round 4
// speedup vs baseline: 1.8377x; 1.6233x over previous
#include <cuda_runtime.h>
#include <cuda_bf16.h>
#include <math.h>
#include <stdint.h>

// Problem dims
constexpr int Bn = 2, Sn = 2048, Hn = 4096, NHn = 32, NKVn = 8, HDn = 128;
constexpr int Mn = Bn * Sn;            // 4096 rows of X
constexpr float QK_SCALE = 0.08838834764831845f; // 1/sqrt(128)

// fp32 scratch (allocation-free: __device__ globals)
__device__ float g_Q[(size_t)Bn * NHn * Sn * HDn];   // [b][h][s][d]
__device__ float g_K[(size_t)Bn * NKVn * Sn * HDn];  // [b][kh][s][d]
__device__ float g_V[(size_t)Bn * NKVn * Sn * HDn];
__device__ float g_A[(size_t)Bn * Sn * NHn * HDn];   // [b][s][h*d]

// bf16 split scratch
__device__ __nv_bfloat16 g_Xhi[(size_t)Mn * Hn];
__device__ __nv_bfloat16 g_Xlo[(size_t)Mn * Hn];
__device__ __nv_bfloat16 g_WqThi[(size_t)4096 * 4096];
__device__ __nv_bfloat16 g_WqTlo[(size_t)4096 * 4096];
__device__ __nv_bfloat16 g_WkThi[(size_t)1024 * 4096];
__device__ __nv_bfloat16 g_WkTlo[(size_t)1024 * 4096];
__device__ __nv_bfloat16 g_WvThi[(size_t)1024 * 4096];
__device__ __nv_bfloat16 g_WvTlo[(size_t)1024 * 4096];
__device__ __nv_bfloat16 g_WoThi[(size_t)4096 * 4096];
__device__ __nv_bfloat16 g_WoTlo[(size_t)4096 * 4096];

// ---------------------------------------------------------------------------
// helpers
// ---------------------------------------------------------------------------
__device__ __forceinline__ uint32_t smem_u32(const void* p) {
    uint32_t a;
    asm("{ .reg .u64 t; cvta.to.shared.u64 t, %1; cvt.u32.u64 %0, t; }"
        : "=r"(a) : "l"(p));
    return a;
}

__device__ __forceinline__ void cpa16(uint32_t dst, const void* src) {
    asm volatile("cp.async.cg.shared.global [%0], [%1], 16;"
                 :: "r"(dst), "l"(src) : "memory");
}

__device__ __forceinline__ void ldsm4(uint32_t& r0, uint32_t& r1,
                                      uint32_t& r2, uint32_t& r3, uint32_t a) {
    asm volatile("ldmatrix.sync.aligned.m8n8.x4.shared.b16 {%0,%1,%2,%3}, [%4];"
                 : "=r"(r0), "=r"(r1), "=r"(r2), "=r"(r3) : "r"(a));
}

__device__ __forceinline__ void mma_bf16(float* c, const uint32_t* a,
                                         const uint32_t* b) {
    asm volatile(
        "mma.sync.aligned.m16n8k16.row.col.f32.bf16.bf16.f32 "
        "{%0,%1,%2,%3}, {%4,%5,%6,%7}, {%8,%9}, {%0,%1,%2,%3};"
        : "+f"(c[0]), "+f"(c[1]), "+f"(c[2]), "+f"(c[3])
        : "r"(a[0]), "r"(a[1]), "r"(a[2]), "r"(a[3]), "r"(b[0]), "r"(b[1]));
}

// ---------------------------------------------------------------------------
// Split conversion: x -> (hi, lo) bf16
// ---------------------------------------------------------------------------
__global__ void split_kernel(const float* __restrict__ x,
                             __nv_bfloat16* __restrict__ hi,
                             __nv_bfloat16* __restrict__ lo, int n4)
{
    int i = blockIdx.x * 256 + threadIdx.x;
    if (i >= n4) return;
    float4 v = reinterpret_cast<const float4*>(x)[i];
    __nv_bfloat16 h0 = __float2bfloat16(v.x), h1 = __float2bfloat16(v.y);
    __nv_bfloat16 h2 = __float2bfloat16(v.z), h3 = __float2bfloat16(v.w);
    __nv_bfloat16 l0 = __float2bfloat16(v.x - __bfloat162float(h0));
    __nv_bfloat16 l1 = __float2bfloat16(v.y - __bfloat162float(h1));
    __nv_bfloat16 l2 = __float2bfloat16(v.z - __bfloat162float(h2));
    __nv_bfloat16 l3 = __float2bfloat16(v.w - __bfloat162float(h3));
    reinterpret_cast<__nv_bfloat162*>(hi)[i * 2 + 0] = __halves2bfloat162(h0, h1);
    reinterpret_cast<__nv_bfloat162*>(hi)[i * 2 + 1] = __halves2bfloat162(h2, h3);
    reinterpret_cast<__nv_bfloat162*>(lo)[i * 2 + 0] = __halves2bfloat162(l0, l1);
    reinterpret_cast<__nv_bfloat162*>(lo)[i * 2 + 1] = __halves2bfloat162(l2, l3);
}

// ---------------------------------------------------------------------------
// Transpose + split: W[K][N] fp32 -> T{hi,lo}[N][K] bf16
// ---------------------------------------------------------------------------
__global__ void tsplit_kernel(const float* __restrict__ W,
                              __nv_bfloat16* __restrict__ Thi,
                              __nv_bfloat16* __restrict__ Tlo, int K, int N)
{
    __shared__ float t[32][33];
    int tx = threadIdx.x, ty = threadIdx.y;   // (32, 8)
    int bx = blockIdx.x, by = blockIdx.y;
#pragma unroll
    for (int i = 0; i < 4; i++) {
        int r = by * 32 + ty + i * 8;
        t[ty + i * 8][tx] = W[(size_t)r * N + bx * 32 + tx];
    }
    __syncthreads();
#pragma unroll
    for (int i = 0; i < 4; i++) {
        int n = bx * 32 + ty + i * 8;
        int k = by * 32 + tx;
        float v = t[tx][ty + i * 8];
        __nv_bfloat16 h = __float2bfloat16(v);
        __nv_bfloat16 l = __float2bfloat16(v - __bfloat162float(h));
        Thi[(size_t)n * K + k] = h;
        Tlo[(size_t)n * K + k] = l;
    }
}

// ---------------------------------------------------------------------------
// bf16 split GEMM on mma.sync: C[M,N] = A[M,K] @ B^T
// A=[m][k] hi/lo bf16, BT=[n][k] hi/lo bf16. CTA 128x128, 8 warps (2x4),
// warp tile 64x32. K-chunk 64, cp.async double buffer, ldmatrix fragments.
// 3 passes: Ah*Bh + Ah*Bl + Al*Bh accumulated in fp32.
// MODE 0: C row-major; MODE 1: Q layout [b][h][s][d]; MODE 2: KV layout.
// ---------------------------------------------------------------------------
constexpr int TROW = 144;                 // 128B data + 16B pad per row
constexpr int TTILE = 128 * TROW;         // 18432 B
constexpr int TSTAGE = 4 * TTILE;         // Ah, Al, Bh, Bl
constexpr int HG_SMEM = 2 * TSTAGE;       // 147456 B

template <int MODE>
__global__ __launch_bounds__(256) void hgemm_kernel(
    const __nv_bfloat16* __restrict__ Ahi, const __nv_bfloat16* __restrict__ Alo,
    const __nv_bfloat16* __restrict__ Bhi, const __nv_bfloat16* __restrict__ Blo,
    float* __restrict__ C, int N, int K)
{
    extern __shared__ char smem[];
    const uint32_t sb = smem_u32(smem);

    const int tid = threadIdx.x;
    const int wid = tid >> 5, lane = tid & 31;
    const int g = lane >> 2, t4 = lane & 3;
    const int wr = wid >> 2, wc = wid & 3;
    const int wm = wr * 64, wn = wc * 32;
    const int m0 = blockIdx.y * 128, n0 = blockIdx.x * 128;

    const __nv_bfloat16* Ah = Ahi + (size_t)m0 * K;
    const __nv_bfloat16* Al = Alo + (size_t)m0 * K;
    const __nv_bfloat16* Bh = Bhi + (size_t)n0 * K;
    const __nv_bfloat16* Bl = Blo + (size_t)n0 * K;

    float c[4][4][4];
#pragma unroll
    for (int mi = 0; mi < 4; mi++)
#pragma unroll
        for (int ni = 0; ni < 4; ni++)
#pragma unroll
            for (int r = 0; r < 4; r++) c[mi][ni][r] = 0.f;

    const int rb = tid >> 3;          // 0..31
    const int c8 = tid & 7;           // 16B chunk within 128B row

    auto load_chunk = [&](int stage, int koff) {
        const uint32_t base = sb + stage * TSTAGE;
#pragma unroll
        for (int i = 0; i < 16; i++) {
            const int tile = i >> 2;
            const int r = (i & 3) * 32 + rb;
            const __nv_bfloat16* s =
                (tile == 0) ? Ah : (tile == 1) ? Al : (tile == 2) ? Bh : Bl;
            cpa16(base + tile * TTILE + r * TROW + c8 * 16,
                  s + (size_t)r * K + koff + c8 * 8);
        }
        asm volatile("cp.async.commit_group;" ::: "memory");
    };

    const int NC = K / 64;
    load_chunk(0, 0);
    if (NC > 1) load_chunk(1, 64);

    // ldmatrix lane address offsets
    const int arow_off = (lane & 7) + ((lane >> 3) & 1) * 8; // A: row within m16
    const int acol_off = (lane >> 4) * 8;                    // A: k half
    const int brow_off = (lane & 7) + (lane >> 4) * 8;       // B: row within n16
    const int bcol_off = ((lane >> 3) & 1) * 8;              // B: k half

    for (int ch = 0; ch < NC; ch++) {
        if (ch + 1 < NC)
            asm volatile("cp.async.wait_group 1;" ::: "memory");
        else
            asm volatile("cp.async.wait_group 0;" ::: "memory");
        __syncthreads();

        const uint32_t st = sb + (ch & 1) * TSTAGE;
        const uint32_t ah_b = st, al_b = st + TTILE;
        const uint32_t bh_b = st + 2 * TTILE, bl_b = st + 3 * TTILE;

#pragma unroll
        for (int kk = 0; kk < 64; kk += 16) {
            uint32_t fah[4][4], fal[4][4], fbh[4][2], fbl[4][2];
#pragma unroll
            for (int mi = 0; mi < 4; mi++) {
                const uint32_t ro = (wm + mi * 16 + arow_off) * TROW +
                                    (kk + acol_off) * 2;
                ldsm4(fah[mi][0], fah[mi][1], fah[mi][2], fah[mi][3], ah_b + ro);
                ldsm4(fal[mi][0], fal[mi][1], fal[mi][2], fal[mi][3], al_b + ro);
            }
#pragma unroll
            for (int bt = 0; bt < 2; bt++) {
                const uint32_t ro = (wn + bt * 16 + brow_off) * TROW +
                                    (kk + bcol_off) * 2;
                ldsm4(fbh[2 * bt][0], fbh[2 * bt][1],
                      fbh[2 * bt + 1][0], fbh[2 * bt + 1][1], bh_b + ro);
                ldsm4(fbl[2 * bt][0], fbl[2 * bt][1],
                      fbl[2 * bt + 1][0], fbl[2 * bt + 1][1], bl_b + ro);
            }
#pragma unroll
            for (int mi = 0; mi < 4; mi++)
#pragma unroll
                for (int ni = 0; ni < 4; ni++) {
                    mma_bf16(c[mi][ni], fah[mi], fbh[ni]);
                    mma_bf16(c[mi][ni], fah[mi], fbl[ni]);
                    mma_bf16(c[mi][ni], fal[mi], fbh[ni]);
                }
        }
        __syncthreads();
        if (ch + 2 < NC) load_chunk(ch & 1, (ch + 2) * 64);
    }

    // Epilogue: c-frag (g,2t4),(g,2t4+1),(g+8,2t4),(g+8,2t4+1)
#pragma unroll
    for (int mi = 0; mi < 4; mi++) {
#pragma unroll
        for (int ni = 0; ni < 4; ni++) {
            const int row0 = m0 + wm + mi * 16 + g;
            const int col = n0 + wn + ni * 8 + 2 * t4;
#pragma unroll
            for (int half = 0; half < 2; half++) {
                const int m = row0 + half * 8;
                float2 v = half ? make_float2(c[mi][ni][2], c[mi][ni][3])
                                : make_float2(c[mi][ni][0], c[mi][ni][1]);
                if (MODE == 0) {
                    *reinterpret_cast<float2*>(&C[(size_t)m * N + col]) = v;
                } else if (MODE == 1) {
                    int b = m >> 11, s = m & 2047;
                    int h = col >> 7, d = col & 127;
                    *reinterpret_cast<float2*>(
                        &C[(((size_t)(b * NHn + h) * Sn) + s) * HDn + d]) = v;
                } else {
                    int b = m >> 11, s = m & 2047;
                    int h = col >> 7, d = col & 127;
                    *reinterpret_cast<float2*>(
                        &C[(((size_t)(b * NKVn + h) * Sn) + s) * HDn + d]) = v;
                }
            }
        }
    }
}

// ---------------------------------------------------------------------------
// RoPE (in place, [bh][s][128] layout). pos == s (position_ids is arange).
// ---------------------------------------------------------------------------
__global__ void rope_kernel(float* __restrict__ X, int total)
{
    int idx = blockIdx.x * 256 + threadIdx.x;
    if (idx >= total) return;
    int d = idx & 63;
    int s = (idx >> 6) & (Sn - 1);
    int bh = idx >> 17;
    float inv = powf(10000.f, -(float)d / 64.f);
    float ang = (float)s * inv;
    float sn, cs;
    sincosf(ang, &sn, &cs);
    size_t base = ((size_t)bh * Sn + s) * HDn;
    float x0 = X[base + d];
    float x1 = X[base + d + 64];
    X[base + d]      = x0 * cs - x1 * sn;
    X[base + d + 64] = x1 * cs + x0 * sn;
}

// ---------------------------------------------------------------------------
// Flash attention, fp32, BQ=BK=64, 256 threads (proven round-1/2 version).
// ---------------------------------------------------------------------------
constexpr int BQ = 64, BK = 64, KTP = 68;
constexpr int ATTN_SMEM = (BQ * HDn + HDn * KTP + BK * HDn) * 4; // 100352 B

__global__ __launch_bounds__(256, 2) void attn_kernel()
{
    extern __shared__ float sm[];
    float* Qs = sm;
    float* Kt = Qs + BQ * HDn;
    float* Vs = Kt + HDn * KTP;
    float* Ss = Kt;

    const int qt = blockIdx.x, h = blockIdx.y, b = blockIdx.z;
    const int tid = threadIdx.x;
    const int tx = tid & 15, ty = tid >> 4;
    const int kvh = h >> 2;

    const float* Qg = g_Q + ((size_t)(b * NHn + h) * Sn + qt * BQ) * HDn;
    const float* Kg = g_K + ((size_t)(b * NKVn + kvh) * Sn) * HDn;
    const float* Vg = g_V + ((size_t)(b * NKVn + kvh) * Sn) * HDn;

    for (int i = tid; i < BQ * HDn; i += 256) Qs[i] = Qg[i] * QK_SCALE;

    float acc[4][8];
#pragma unroll
    for (int i = 0; i < 4; i++)
#pragma unroll
        for (int j = 0; j < 8; j++) acc[i][j] = 0.f;
    float mi[4] = {-1e30f, -1e30f, -1e30f, -1e30f};
    float li[4] = {0.f, 0.f, 0.f, 0.f};

    const int nkt = qt + 1;
    for (int kt = 0; kt < nkt; kt++) {
        __syncthreads();
        const float* Ktile = Kg + (size_t)kt * BK * HDn;
        const float* Vtile = Vg + (size_t)kt * BK * HDn;
        for (int i = tid; i < BK * HDn; i += 256) {
            int r = i >> 7, d = i & 127;
            Kt[d * KTP + r] = Ktile[i];
            Vs[i] = Vtile[i];
        }
        __syncthreads();

        float sc[4][4];
#pragma unroll
        for (int i = 0; i < 4; i++)
#pragma unroll
            for (int j = 0; j < 4; j++) sc[i][j] = 0.f;

#pragma unroll 4
        for (int d = 0; d < HDn; d++) {
            float4 kv = *reinterpret_cast<const float4*>(&Kt[d * KTP + tx * 4]);
            float q0 = Qs[(ty * 4 + 0) * HDn + d];
            float q1 = Qs[(ty * 4 + 1) * HDn + d];
            float q2 = Qs[(ty * 4 + 2) * HDn + d];
            float q3 = Qs[(ty * 4 + 3) * HDn + d];
            sc[0][0] = fmaf(q0, kv.x, sc[0][0]); sc[0][1] = fmaf(q0, kv.y, sc[0][1]);
            sc[0][2] = fmaf(q0, kv.z, sc[0][2]); sc[0][3] = fmaf(q0, kv.w, sc[0][3]);
            sc[1][0] = fmaf(q1, kv.x, sc[1][0]); sc[1][1] = fmaf(q1, kv.y, sc[1][1]);
            sc[1][2] = fmaf(q1, kv.z, sc[1][2]); sc[1][3] = fmaf(q1, kv.w, sc[1][3]);
            sc[2][0] = fmaf(q2, kv.x, sc[2][0]); sc[2][1] = fmaf(q2, kv.y, sc[2][1]);
            sc[2][2] = fmaf(q2, kv.z, sc[2][2]); sc[2][3] = fmaf(q2, kv.w, sc[2][3]);
            sc[3][0] = fmaf(q3, kv.x, sc[3][0]); sc[3][1] = fmaf(q3, kv.y, sc[3][1]);
            sc[3][2] = fmaf(q3, kv.z, sc[3][2]); sc[3][3] = fmaf(q3, kv.w, sc[3][3]);
        }

        if (kt == qt) {
            int qg0 = qt * BQ + ty * 4;
            int kg0 = kt * BK + tx * 4;
#pragma unroll
            for (int i = 0; i < 4; i++)
#pragma unroll
                for (int j = 0; j < 4; j++)
                    if (kg0 + j > qg0 + i) sc[i][j] = -1e30f;
        }

#pragma unroll
        for (int i = 0; i < 4; i++) {
            float tm = fmaxf(fmaxf(sc[i][0], sc[i][1]), fmaxf(sc[i][2], sc[i][3]));
#pragma unroll
            for (int o = 8; o >= 1; o >>= 1)
                tm = fmaxf(tm, __shfl_xor_sync(0xffffffffu, tm, o));
            float mnew = fmaxf(mi[i], tm);
            float corr = __expf(mi[i] - mnew);
            mi[i] = mnew;
            li[i] *= corr;
#pragma unroll
            for (int j = 0; j < 8; j++) acc[i][j] *= corr;
            float rs = 0.f;
#pragma unroll
            for (int j = 0; j < 4; j++) {
                sc[i][j] = __expf(sc[i][j] - mnew);
                rs += sc[i][j];
            }
#pragma unroll
            for (int o = 8; o >= 1; o >>= 1)
                rs += __shfl_xor_sync(0xffffffffu, rs, o);
            li[i] += rs;
        }

        __syncthreads();
#pragma unroll
        for (int i = 0; i < 4; i++)
#pragma unroll
            for (int j = 0; j < 4; j++)
                Ss[(ty * 4 + i) * BK + tx * 4 + j] = sc[i][j];
        __syncthreads();

#pragma unroll 2
        for (int k = 0; k < BK; k++) {
            float4 v0 = *reinterpret_cast<const float4*>(&Vs[k * HDn + tx * 4]);
            float4 v1 = *reinterpret_cast<const float4*>(&Vs[k * HDn + 64 + tx * 4]);
            float p0 = Ss[(ty * 4 + 0) * BK + k];
            float p1 = Ss[(ty * 4 + 1) * BK + k];
            float p2 = Ss[(ty * 4 + 2) * BK + k];
            float p3 = Ss[(ty * 4 + 3) * BK + k];
            acc[0][0] = fmaf(p0, v0.x, acc[0][0]); acc[0][1] = fmaf(p0, v0.y, acc[0][1]);
            acc[0][2] = fmaf(p0, v0.z, acc[0][2]); acc[0][3] = fmaf(p0, v0.w, acc[0][3]);
            acc[0][4] = fmaf(p0, v1.x, acc[0][4]); acc[0][5] = fmaf(p0, v1.y, acc[0][5]);
            acc[0][6] = fmaf(p0, v1.z, acc[0][6]); acc[0][7] = fmaf(p0, v1.w, acc[0][7]);
            acc[1][0] = fmaf(p1, v0.x, acc[1][0]); acc[1][1] = fmaf(p1, v0.y, acc[1][1]);
            acc[1][2] = fmaf(p1, v0.z, acc[1][2]); acc[1][3] = fmaf(p1, v0.w, acc[1][3]);
            acc[1][4] = fmaf(p1, v1.x, acc[1][4]); acc[1][5] = fmaf(p1, v1.y, acc[1][5]);
            acc[1][6] = fmaf(p1, v1.z, acc[1][6]); acc[1][7] = fmaf(p1, v1.w, acc[1][7]);
            acc[2][0] = fmaf(p2, v0.x, acc[2][0]); acc[2][1] = fmaf(p2, v0.y, acc[2][1]);
            acc[2][2] = fmaf(p2, v0.z, acc[2][2]); acc[2][3] = fmaf(p2, v0.w, acc[2][3]);
            acc[2][4] = fmaf(p2, v1.x, acc[2][4]); acc[2][5] = fmaf(p2, v1.y, acc[2][5]);
            acc[2][6] = fmaf(p2, v1.z, acc[2][6]); acc[2][7] = fmaf(p2, v1.w, acc[2][7]);
            acc[3][0] = fmaf(p3, v0.x, acc[3][0]); acc[3][1] = fmaf(p3, v0.y, acc[3][1]);
            acc[3][2] = fmaf(p3, v0.z, acc[3][2]); acc[3][3] = fmaf(p3, v0.w, acc[3][3]);
            acc[3][4] = fmaf(p3, v1.x, acc[3][4]); acc[3][5] = fmaf(p3, v1.y, acc[3][5]);
            acc[3][6] = fmaf(p3, v1.z, acc[3][6]); acc[3][7] = fmaf(p3, v1.w, acc[3][7]);
        }
    }

    float* Og = g_A + ((size_t)(b * Sn + qt * BQ)) * (NHn * HDn) + h * HDn;
#pragma unroll
    for (int i = 0; i < 4; i++) {
        int r = ty * 4 + i;
        float inv = 1.f / li[i];
        float* row = Og + (size_t)r * (NHn * HDn);
#pragma unroll
        for (int j = 0; j < 4; j++) {
            row[tx * 4 + j] = acc[i][j] * inv;
            row[64 + tx * 4 + j] = acc[i][4 + j] * inv;
        }
    }
}

// ---------------------------------------------------------------------------
extern "C" void kernel_launch(void* const* d_in, const int* in_sizes, int n_in,
                              void* d_out, int out_size)
{
    const float* hidden = (const float*)d_in[0];
    // d_in[1] = position_ids (broadcast arange; pos == s, derived in-kernel)
    const float* Wq = (const float*)d_in[2];
    const float* Wk = (const float*)d_in[3];
    const float* Wv = (const float*)d_in[4];
    const float* Wo = (const float*)d_in[5];
    float* out = (float*)d_out;

    float *pQ, *pK, *pV, *pA;
    __nv_bfloat16 *pXh, *pXl, *pQTh, *pQTl, *pKTh, *pKTl, *pVTh, *pVTl, *pOTh, *pOTl;
    cudaGetSymbolAddress((void**)&pQ, g_Q);
    cudaGetSymbolAddress((void**)&pK, g_K);
    cudaGetSymbolAddress((void**)&pV, g_V);
    cudaGetSymbolAddress((void**)&pA, g_A);
    cudaGetSymbolAddress((void**)&pXh, g_Xhi);
    cudaGetSymbolAddress((void**)&pXl, g_Xlo);
    cudaGetSymbolAddress((void**)&pQTh, g_WqThi);
    cudaGetSymbolAddress((void**)&pQTl, g_WqTlo);
    cudaGetSymbolAddress((void**)&pKTh, g_WkThi);
    cudaGetSymbolAddress((void**)&pKTl, g_WkTlo);
    cudaGetSymbolAddress((void**)&pVTh, g_WvThi);
    cudaGetSymbolAddress((void**)&pVTl, g_WvTlo);
    cudaGetSymbolAddress((void**)&pOTh, g_WoThi);
    cudaGetSymbolAddress((void**)&pOTl, g_WoTlo);

    cudaFuncSetAttribute(attn_kernel,
                         cudaFuncAttributeMaxDynamicSharedMemorySize, ATTN_SMEM);
    cudaFuncSetAttribute(hgemm_kernel<0>,
                         cudaFuncAttributeMaxDynamicSharedMemorySize, HG_SMEM);
    cudaFuncSetAttribute(hgemm_kernel<1>,
                         cudaFuncAttributeMaxDynamicSharedMemorySize, HG_SMEM);
    cudaFuncSetAttribute(hgemm_kernel<2>,
                         cudaFuncAttributeMaxDynamicSharedMemorySize, HG_SMEM);

    // 0) split/transpose conversions
    const int n4x = Mn * Hn / 4;
    split_kernel<<<n4x / 256, 256>>>(hidden, pXh, pXl, n4x);
    dim3 tb(32, 8);
    tsplit_kernel<<<dim3(4096 / 32, 4096 / 32), tb>>>(Wq, pQTh, pQTl, Hn, 4096);
    tsplit_kernel<<<dim3(1024 / 32, 4096 / 32), tb>>>(Wk, pKTh, pKTl, Hn, 1024);
    tsplit_kernel<<<dim3(1024 / 32, 4096 / 32), tb>>>(Wv, pVTh, pVTl, Hn, 1024);
    tsplit_kernel<<<dim3(4096 / 32, 4096 / 32), tb>>>(Wo, pOTh, pOTl, 4096, Hn);

    // 1) projections (bf16 split mma)
    hgemm_kernel<1><<<dim3(4096 / 128, Mn / 128), 256, HG_SMEM>>>(
        pXh, pXl, pQTh, pQTl, pQ, 4096, Hn);
    hgemm_kernel<2><<<dim3(1024 / 128, Mn / 128), 256, HG_SMEM>>>(
        pXh, pXl, pKTh, pKTl, pK, 1024, Hn);
    hgemm_kernel<2><<<dim3(1024 / 128, Mn / 128), 256, HG_SMEM>>>(
        pXh, pXl, pVTh, pVTl, pV, 1024, Hn);

    // 2) RoPE on Q and K
    int totQ = Bn * NHn * Sn * 64;
    int totK = Bn * NKVn * Sn * 64;
    rope_kernel<<<totQ / 256, 256>>>(pQ, totQ);
    rope_kernel<<<totK / 256, 256>>>(pK, totK);

    // 3) causal flash attention (fp32 SIMT)
    dim3 ga(Sn / BQ, NHn, Bn);
    attn_kernel<<<ga, 256, ATTN_SMEM>>>();

    // 4) output projection: split g_A then bf16 split mma
    split_kernel<<<n4x / 256, 256>>>(pA, pXh, pXl, n4x);
    hgemm_kernel<0><<<dim3(4096 / 128, Mn / 128), 256, HG_SMEM>>>(
        pXh, pXl, pOTh, pOTl, out, 4096, Hn);
}

// round 6
// speedup vs baseline: 2.6151x; 1.4231x over previous
#include <cuda_runtime.h>
#include <cuda_bf16.h>
#include <math.h>
#include <stdint.h>

// Problem dims
constexpr int Bn = 2, Sn = 2048, Hn = 4096, NHn = 32, NKVn = 8, HDn = 128;
constexpr int Mn = Bn * Sn;
constexpr float QK_SCALE = 0.08838834764831845f; // 1/sqrt(128)
constexpr float L2E = 1.4426950408889634f;

// fp32 scratch
__device__ float g_Q[(size_t)Bn * NHn * Sn * HDn];   // [b][h][s][d]
__device__ float g_K[(size_t)Bn * NKVn * Sn * HDn];  // [b][kh][s][d]
__device__ float g_V[(size_t)Bn * NKVn * Sn * HDn];
__device__ float g_A[(size_t)Bn * Sn * NHn * HDn];   // [b][s][h*d]

// bf16 split scratch
__device__ __nv_bfloat16 g_Xhi[(size_t)Mn * Hn];
__device__ __nv_bfloat16 g_Xlo[(size_t)Mn * Hn];
__device__ __nv_bfloat16 g_WqThi[(size_t)4096 * 4096];
__device__ __nv_bfloat16 g_WqTlo[(size_t)4096 * 4096];
__device__ __nv_bfloat16 g_WkThi[(size_t)1024 * 4096];
__device__ __nv_bfloat16 g_WkTlo[(size_t)1024 * 4096];
__device__ __nv_bfloat16 g_WvThi[(size_t)1024 * 4096];
__device__ __nv_bfloat16 g_WvTlo[(size_t)1024 * 4096];
__device__ __nv_bfloat16 g_WoThi[(size_t)4096 * 4096];
__device__ __nv_bfloat16 g_WoTlo[(size_t)4096 * 4096];
// attention operands (hi/lo, post-RoPE)
__device__ __nv_bfloat16 g_Qh[(size_t)Bn * NHn * Sn * HDn];
__device__ __nv_bfloat16 g_Ql[(size_t)Bn * NHn * Sn * HDn];
__device__ __nv_bfloat16 g_Kh[(size_t)Bn * NKVn * Sn * HDn];
__device__ __nv_bfloat16 g_Kl[(size_t)Bn * NKVn * Sn * HDn];
__device__ __nv_bfloat16 g_Vh[(size_t)Bn * NKVn * Sn * HDn];
__device__ __nv_bfloat16 g_Vl[(size_t)Bn * NKVn * Sn * HDn];

// ---------------------------------------------------------------------------
// helpers
// ---------------------------------------------------------------------------
__device__ __forceinline__ uint32_t smem_u32(const void* p) {
    uint32_t a;
    asm("{ .reg .u64 t; cvta.to.shared.u64 t, %1; cvt.u32.u64 %0, t; }"
        : "=r"(a) : "l"(p));
    return a;
}
__device__ __forceinline__ void cpa16(uint32_t dst, const void* src) {
    asm volatile("cp.async.cg.shared.global [%0], [%1], 16;"
                 :: "r"(dst), "l"(src) : "memory");
}
__device__ __forceinline__ void ldsm4(uint32_t& r0, uint32_t& r1,
                                      uint32_t& r2, uint32_t& r3, uint32_t a) {
    asm volatile("ldmatrix.sync.aligned.m8n8.x4.shared.b16 {%0,%1,%2,%3}, [%4];"
                 : "=r"(r0), "=r"(r1), "=r"(r2), "=r"(r3) : "r"(a));
}
__device__ __forceinline__ void ldsm4t(uint32_t& r0, uint32_t& r1,
                                       uint32_t& r2, uint32_t& r3, uint32_t a) {
    asm volatile("ldmatrix.sync.aligned.m8n8.x4.trans.shared.b16 {%0,%1,%2,%3}, [%4];"
                 : "=r"(r0), "=r"(r1), "=r"(r2), "=r"(r3) : "r"(a));
}
__device__ __forceinline__ void mma_bf16(float* c, const uint32_t* a,
                                         const uint32_t* b) {
    asm volatile(
        "mma.sync.aligned.m16n8k16.row.col.f32.bf16.bf16.f32 "
        "{%0,%1,%2,%3}, {%4,%5,%6,%7}, {%8,%9}, {%0,%1,%2,%3};"
        : "+f"(c[0]), "+f"(c[1]), "+f"(c[2]), "+f"(c[3])
        : "r"(a[0]), "r"(a[1]), "r"(a[2]), "r"(a[3]), "r"(b[0]), "r"(b[1]));
}
// fast exp2 on the FMA pipe (y <= 0; clamp makes masked rows vanish)
__device__ __forceinline__ float fexp2(float y) {
    y = fmaxf(y, -126.f);
    float fl = floorf(y);
    float f = y - fl;
    float p = 1.8775767e-3f;
    p = fmaf(p, f, 8.9893397e-3f);
    p = fmaf(p, f, 5.5826318e-2f);
    p = fmaf(p, f, 2.4015361e-1f);
    p = fmaf(p, f, 6.9315308e-1f);
    p = fmaf(p, f, 9.9999994e-1f);
    return __int_as_float(((int)fl + 127) << 23) * p;
}
__device__ __forceinline__ uint32_t pack_bf2(float a, float b) {
    __nv_bfloat162 v = __floats2bfloat162_rn(a, b);
    return *reinterpret_cast<uint32_t*>(&v);
}
__device__ __forceinline__ uint32_t pack_bf2_res(float a, float b, uint32_t hi) {
    __nv_bfloat162 hv = *reinterpret_cast<__nv_bfloat162*>(&hi);
    return pack_bf2(a - __bfloat162float(hv.x), b - __bfloat162float(hv.y));
}

// ---------------------------------------------------------------------------
// Split conversion: x -> (hi, lo) bf16
// ---------------------------------------------------------------------------
__global__ void split_kernel(const float* __restrict__ x,
                             __nv_bfloat16* __restrict__ hi,
                             __nv_bfloat16* __restrict__ lo, int n4)
{
    int i = blockIdx.x * 256 + threadIdx.x;
    if (i >= n4) return;
    float4 v = reinterpret_cast<const float4*>(x)[i];
    __nv_bfloat16 h0 = __float2bfloat16(v.x), h1 = __float2bfloat16(v.y);
    __nv_bfloat16 h2 = __float2bfloat16(v.z), h3 = __float2bfloat16(v.w);
    __nv_bfloat16 l0 = __float2bfloat16(v.x - __bfloat162float(h0));
    __nv_bfloat16 l1 = __float2bfloat16(v.y - __bfloat162float(h1));
    __nv_bfloat16 l2 = __float2bfloat16(v.z - __bfloat162float(h2));
    __nv_bfloat16 l3 = __float2bfloat16(v.w - __bfloat162float(h3));
    reinterpret_cast<__nv_bfloat162*>(hi)[i * 2 + 0] = __halves2bfloat162(h0, h1);
    reinterpret_cast<__nv_bfloat162*>(hi)[i * 2 + 1] = __halves2bfloat162(h2, h3);
    reinterpret_cast<__nv_bfloat162*>(lo)[i * 2 + 0] = __halves2bfloat162(l0, l1);
    reinterpret_cast<__nv_bfloat162*>(lo)[i * 2 + 1] = __halves2bfloat162(l2, l3);
}

// ---------------------------------------------------------------------------
// Transpose + split: W[K][N] fp32 -> T{hi,lo}[N][K] bf16
// ---------------------------------------------------------------------------
__global__ void tsplit_kernel(const float* __restrict__ W,
                              __nv_bfloat16* __restrict__ Thi,
                              __nv_bfloat16* __restrict__ Tlo, int K, int N)
{
    __shared__ float t[32][33];
    int tx = threadIdx.x, ty = threadIdx.y;
    int bx = blockIdx.x, by = blockIdx.y;
#pragma unroll
    for (int i = 0; i < 4; i++) {
        int r = by * 32 + ty + i * 8;
        t[ty + i * 8][tx] = W[(size_t)r * N + bx * 32 + tx];
    }
    __syncthreads();
#pragma unroll
    for (int i = 0; i < 4; i++) {
        int n = bx * 32 + ty + i * 8;
        int k = by * 32 + tx;
        float v = t[tx][ty + i * 8];
        __nv_bfloat16 h = __float2bfloat16(v);
        __nv_bfloat16 l = __float2bfloat16(v - __bfloat162float(h));
        Thi[(size_t)n * K + k] = h;
        Tlo[(size_t)n * K + k] = l;
    }
}

// ---------------------------------------------------------------------------
// RoPE + hi/lo split (+ optional scale), [bh][s][128] layout, pos == s.
// ---------------------------------------------------------------------------
__global__ void rope_split_kernel(const float* __restrict__ X,
                                  __nv_bfloat16* __restrict__ H,
                                  __nv_bfloat16* __restrict__ L,
                                  int total, float scale)
{
    int idx = blockIdx.x * 256 + threadIdx.x;
    if (idx >= total) return;
    int d = idx & 63;
    int s = (idx >> 6) & (Sn - 1);
    int bh = idx >> 17;
    float inv = powf(10000.f, -(float)d / 64.f);
    float ang = (float)s * inv;
    float sn, cs;
    sincosf(ang, &sn, &cs);
    size_t base = ((size_t)bh * Sn + s) * HDn;
    float x0 = X[base + d];
    float x1 = X[base + d + 64];
    float r0 = (x0 * cs - x1 * sn) * scale;
    float r1 = (x1 * cs + x0 * sn) * scale;
    __nv_bfloat16 h0 = __float2bfloat16(r0);
    __nv_bfloat16 h1 = __float2bfloat16(r1);
    H[base + d] = h0;
    H[base + d + 64] = h1;
    L[base + d] = __float2bfloat16(r0 - __bfloat162float(h0));
    L[base + d + 64] = __float2bfloat16(r1 - __bfloat162float(h1));
}

// ---------------------------------------------------------------------------
// bf16 split GEMM on mma.sync (unchanged, proven round 4)
// ---------------------------------------------------------------------------
constexpr int TROW = 144;
constexpr int TTILE = 128 * TROW;
constexpr int TSTAGE = 4 * TTILE;
constexpr int HG_SMEM = 2 * TSTAGE;

template <int MODE>
__global__ __launch_bounds__(256) void hgemm_kernel(
    const __nv_bfloat16* __restrict__ Ahi, const __nv_bfloat16* __restrict__ Alo,
    const __nv_bfloat16* __restrict__ Bhi, const __nv_bfloat16* __restrict__ Blo,
    float* __restrict__ C, int N, int K)
{
    extern __shared__ char smem[];
    const uint32_t sb = smem_u32(smem);

    const int tid = threadIdx.x;
    const int wid = tid >> 5, lane = tid & 31;
    const int g = lane >> 2, t4 = lane & 3;
    const int wr = wid >> 2, wc = wid & 3;
    const int wm = wr * 64, wn = wc * 32;
    const int m0 = blockIdx.y * 128, n0 = blockIdx.x * 128;

    const __nv_bfloat16* Ah = Ahi + (size_t)m0 * K;
    const __nv_bfloat16* Al = Alo + (size_t)m0 * K;
    const __nv_bfloat16* Bh = Bhi + (size_t)n0 * K;
    const __nv_bfloat16* Bl = Blo + (size_t)n0 * K;

    float c[4][4][4];
#pragma unroll
    for (int mi = 0; mi < 4; mi++)
#pragma unroll
        for (int ni = 0; ni < 4; ni++)
#pragma unroll
            for (int r = 0; r < 4; r++) c[mi][ni][r] = 0.f;

    const int rb = tid >> 3;
    const int c8 = tid & 7;

    auto load_chunk = [&](int stage, int koff) {
        const uint32_t base = sb + stage * TSTAGE;
#pragma unroll
        for (int i = 0; i < 16; i++) {
            const int tile = i >> 2;
            const int r = (i & 3) * 32 + rb;
            const __nv_bfloat16* s =
                (tile == 0) ? Ah : (tile == 1) ? Al : (tile == 2) ? Bh : Bl;
            cpa16(base + tile * TTILE + r * TROW + c8 * 16,
                  s + (size_t)r * K + koff + c8 * 8);
        }
        asm volatile("cp.async.commit_group;" ::: "memory");
    };

    const int NC = K / 64;
    load_chunk(0, 0);
    if (NC > 1) load_chunk(1, 64);

    const int arow_off = (lane & 7) + ((lane >> 3) & 1) * 8;
    const int acol_off = (lane >> 4) * 8;
    const int brow_off = (lane & 7) + (lane >> 4) * 8;
    const int bcol_off = ((lane >> 3) & 1) * 8;

    for (int ch = 0; ch < NC; ch++) {
        if (ch + 1 < NC)
            asm volatile("cp.async.wait_group 1;" ::: "memory");
        else
            asm volatile("cp.async.wait_group 0;" ::: "memory");
        __syncthreads();

        const uint32_t st = sb + (ch & 1) * TSTAGE;
        const uint32_t ah_b = st, al_b = st + TTILE;
        const uint32_t bh_b = st + 2 * TTILE, bl_b = st + 3 * TTILE;

#pragma unroll
        for (int kk = 0; kk < 64; kk += 16) {
            uint32_t fah[4][4], fal[4][4], fbh[4][2], fbl[4][2];
#pragma unroll
            for (int mi = 0; mi < 4; mi++) {
                const uint32_t ro = (wm + mi * 16 + arow_off) * TROW +
                                    (kk + acol_off) * 2;
                ldsm4(fah[mi][0], fah[mi][1], fah[mi][2], fah[mi][3], ah_b + ro);
                ldsm4(fal[mi][0], fal[mi][1], fal[mi][2], fal[mi][3], al_b + ro);
            }
#pragma unroll
            for (int bt = 0; bt < 2; bt++) {
                const uint32_t ro = (wn + bt * 16 + brow_off) * TROW +
                                    (kk + bcol_off) * 2;
                ldsm4(fbh[2 * bt][0], fbh[2 * bt][1],
                      fbh[2 * bt + 1][0], fbh[2 * bt + 1][1], bh_b + ro);
                ldsm4(fbl[2 * bt][0], fbl[2 * bt][1],
                      fbl[2 * bt + 1][0], fbl[2 * bt + 1][1], bl_b + ro);
            }
#pragma unroll
            for (int mi = 0; mi < 4; mi++)
#pragma unroll
                for (int ni = 0; ni < 4; ni++) {
                    mma_bf16(c[mi][ni], fah[mi], fbh[ni]);
                    mma_bf16(c[mi][ni], fah[mi], fbl[ni]);
                    mma_bf16(c[mi][ni], fal[mi], fbh[ni]);
                }
        }
        __syncthreads();
        if (ch + 2 < NC) load_chunk(ch & 1, (ch + 2) * 64);
    }

#pragma unroll
    for (int mi = 0; mi < 4; mi++) {
#pragma unroll
        for (int ni = 0; ni < 4; ni++) {
            const int row0 = m0 + wm + mi * 16 + g;
            const int col = n0 + wn + ni * 8 + 2 * t4;
#pragma unroll
            for (int half = 0; half < 2; half++) {
                const int m = row0 + half * 8;
                float2 v = half ? make_float2(c[mi][ni][2], c[mi][ni][3])
                                : make_float2(c[mi][ni][0], c[mi][ni][1]);
                if (MODE == 0) {
                    *reinterpret_cast<float2*>(&C[(size_t)m * N + col]) = v;
                } else if (MODE == 1) {
                    int b = m >> 11, s = m & 2047;
                    int h = col >> 7, d = col & 127;
                    *reinterpret_cast<float2*>(
                        &C[(((size_t)(b * NHn + h) * Sn) + s) * HDn + d]) = v;
                } else {
                    int b = m >> 11, s = m & 2047;
                    int h = col >> 7, d = col & 127;
                    *reinterpret_cast<float2*>(
                        &C[(((size_t)(b * NKVn + h) * Sn) + s) * HDn + d]) = v;
                }
            }
        }
    }
}

// ---------------------------------------------------------------------------
// Flash attention on mma.sync, bf16 split, BQ=128, BK=64, 8 warps.
// Round-5 design with the tile-loader fix: rows are 128 bf16 = 256 B = 16
// chunks of 16 B (round 5 loaded only 8 -> half the tile was garbage).
// ---------------------------------------------------------------------------
constexpr int ARB = 272;                  // padded row bytes (136 bf16)
constexpr int KVT = 64 * ARB;             // one 64x128 bf16 tile = 17408 B
constexpr int ASTG = 4 * KVT;             // Kh,Kl,Vh,Vl per stage = 69632 B
constexpr int AT_SMEM = 2 * ASTG;         // 139264 B

__global__ __launch_bounds__(256, 1) void attn_mma_kernel()
{
    extern __shared__ char smem[];
    const uint32_t sb = smem_u32(smem);
    const int qt = blockIdx.x, h = blockIdx.y, b = blockIdx.z;
    const int tid = threadIdx.x, wid = tid >> 5, lane = tid & 31;
    const int g = lane >> 2, t4 = lane & 3;
    const int wm = wid * 16;
    const int kvh = h >> 2;
    const int NT = 2 * (qt + 1);

    const __nv_bfloat16* Qhp = g_Qh + ((size_t)(b * NHn + h) * Sn + qt * 128) * HDn;
    const __nv_bfloat16* Qlp = g_Ql + ((size_t)(b * NHn + h) * Sn + qt * 128) * HDn;
    const __nv_bfloat16* Khp = g_Kh + ((size_t)(b * NKVn + kvh) * Sn) * HDn;
    const __nv_bfloat16* Klp = g_Kl + ((size_t)(b * NKVn + kvh) * Sn) * HDn;
    const __nv_bfloat16* Vhp = g_Vh + ((size_t)(b * NKVn + kvh) * Sn) * HDn;
    const __nv_bfloat16* Vlp = g_Vl + ((size_t)(b * NKVn + kvh) * Sn) * HDn;

    // Q tiles -> stage1 region (reused for K/V after frags extracted)
    // 128 rows x 16 chunks(16B) per tile -> 2048 ids
    const uint32_t qhb = sb + ASTG, qlb = sb + ASTG + 34816;
#pragma unroll
    for (int i = 0; i < 8; i++) {
        int id = tid + i * 256, r = id >> 4, c = id & 15;
        cpa16(qhb + r * ARB + c * 16, Qhp + r * HDn + c * 8);
        cpa16(qlb + r * ARB + c * 16, Qlp + r * HDn + c * 8);
    }
    asm volatile("cp.async.commit_group;" ::: "memory");

    auto load_stage = [&](int stg, int t) {
        const uint32_t st = sb + stg * ASTG;
        const __nv_bfloat16* kh = Khp + (size_t)t * 64 * HDn;
        const __nv_bfloat16* kl = Klp + (size_t)t * 64 * HDn;
        const __nv_bfloat16* vh = Vhp + (size_t)t * 64 * HDn;
        const __nv_bfloat16* vl = Vlp + (size_t)t * 64 * HDn;
        // 64 rows x 16 chunks per tile -> 1024 ids, 4 tiles
#pragma unroll
        for (int i = 0; i < 4; i++) {
            int id = tid + i * 256, r = id >> 4, c = id & 15;
            cpa16(st + 0 * KVT + r * ARB + c * 16, kh + r * HDn + c * 8);
            cpa16(st + 1 * KVT + r * ARB + c * 16, kl + r * HDn + c * 8);
            cpa16(st + 2 * KVT + r * ARB + c * 16, vh + r * HDn + c * 8);
            cpa16(st + 3 * KVT + r * ARB + c * 16, vl + r * HDn + c * 8);
        }
        asm volatile("cp.async.commit_group;" ::: "memory");
    };
    load_stage(0, 0);

    asm volatile("cp.async.wait_group 1;" ::: "memory");  // Q arrived
    __syncthreads();

    const int arow = (lane & 7) + ((lane >> 3) & 1) * 8;
    const int acolB = (lane >> 4) * 16;                   // bytes
    uint32_t qhf[8][4], qlf[8][4];
#pragma unroll
    for (int ks = 0; ks < 8; ks++) {
        uint32_t ro = (wm + arow) * ARB + ks * 32 + acolB;
        ldsm4(qhf[ks][0], qhf[ks][1], qhf[ks][2], qhf[ks][3], qhb + ro);
        ldsm4(qlf[ks][0], qlf[ks][1], qlf[ks][2], qlf[ks][3], qlb + ro);
    }
    __syncthreads();          // Q smem free before K1 overwrites it
    load_stage(1, 1);         // NT >= 2 always

    float o[16][4];
#pragma unroll
    for (int j = 0; j < 16; j++)
#pragma unroll
        for (int e = 0; e < 4; e++) o[j][e] = 0.f;
    float m0 = -1e30f, m1 = -1e30f, l0 = 0.f, l1 = 0.f;

    const int brow = (lane & 7) + (lane >> 4) * 8;
    const int bcolB = ((lane >> 3) & 1) * 16;
    const int vcolB = (lane >> 4) * 16;
    const int row0g = qt * 128 + wm + g;

    for (int t = 0; t < NT; t++) {
        if (t + 1 < NT)
            asm volatile("cp.async.wait_group 1;" ::: "memory");
        else
            asm volatile("cp.async.wait_group 0;" ::: "memory");
        __syncthreads();
        const uint32_t st = sb + (t & 1) * ASTG;

        // ---- scores S = Q K^T (3-pass split) ----
        float s[8][4];
#pragma unroll
        for (int j = 0; j < 8; j++)
#pragma unroll
            for (int e = 0; e < 4; e++) s[j][e] = 0.f;

#pragma unroll
        for (int ks = 0; ks < 8; ks++) {
#pragma unroll
            for (int gr = 0; gr < 4; gr++) {
                uint32_t kh4[4], kl4[4];
                uint32_t ro = st + (gr * 16 + brow) * ARB + ks * 32 + bcolB;
                ldsm4(kh4[0], kh4[1], kh4[2], kh4[3], ro);
                ldsm4(kl4[0], kl4[1], kl4[2], kl4[3], ro + KVT);
                mma_bf16(s[2 * gr], qhf[ks], kh4);
                mma_bf16(s[2 * gr], qhf[ks], kl4);
                mma_bf16(s[2 * gr], qlf[ks], kh4);
                mma_bf16(s[2 * gr + 1], qhf[ks], kh4 + 2);
                mma_bf16(s[2 * gr + 1], qhf[ks], kl4 + 2);
                mma_bf16(s[2 * gr + 1], qlf[ks], kh4 + 2);
            }
        }

        // ---- causal mask (diagonal region only) ----
        if (t >= 2 * qt) {
#pragma unroll
            for (int j = 0; j < 8; j++) {
                int c0 = t * 64 + j * 8 + 2 * t4;
                if (c0 > row0g)     s[j][0] = -1e30f;
                if (c0 + 1 > row0g) s[j][1] = -1e30f;
                if (c0 > row0g + 8)     s[j][2] = -1e30f;
                if (c0 + 1 > row0g + 8) s[j][3] = -1e30f;
            }
        }

        // ---- online softmax (fp32, poly exp2 on FMA pipe) ----
        float tm0 = -1e30f, tm1 = -1e30f;
#pragma unroll
        for (int j = 0; j < 8; j++) {
            tm0 = fmaxf(tm0, fmaxf(s[j][0], s[j][1]));
            tm1 = fmaxf(tm1, fmaxf(s[j][2], s[j][3]));
        }
        tm0 = fmaxf(tm0, __shfl_xor_sync(0xffffffffu, tm0, 1));
        tm0 = fmaxf(tm0, __shfl_xor_sync(0xffffffffu, tm0, 2));
        tm1 = fmaxf(tm1, __shfl_xor_sync(0xffffffffu, tm1, 1));
        tm1 = fmaxf(tm1, __shfl_xor_sync(0xffffffffu, tm1, 2));
        float mn0 = fmaxf(m0, tm0), mn1 = fmaxf(m1, tm1);
        float cor0 = fexp2((m0 - mn0) * L2E);
        float cor1 = fexp2((m1 - mn1) * L2E);
        m0 = mn0; m1 = mn1;
#pragma unroll
        for (int j = 0; j < 16; j++) {
            o[j][0] *= cor0; o[j][1] *= cor0;
            o[j][2] *= cor1; o[j][3] *= cor1;
        }
        float rs0 = 0.f, rs1 = 0.f;
#pragma unroll
        for (int j = 0; j < 8; j++) {
            s[j][0] = fexp2((s[j][0] - mn0) * L2E);
            s[j][1] = fexp2((s[j][1] - mn0) * L2E);
            s[j][2] = fexp2((s[j][2] - mn1) * L2E);
            s[j][3] = fexp2((s[j][3] - mn1) * L2E);
            rs0 += s[j][0] + s[j][1];
            rs1 += s[j][2] + s[j][3];
        }
        rs0 += __shfl_xor_sync(0xffffffffu, rs0, 1);
        rs0 += __shfl_xor_sync(0xffffffffu, rs0, 2);
        rs1 += __shfl_xor_sync(0xffffffffu, rs1, 1);
        rs1 += __shfl_xor_sync(0xffffffffu, rs1, 2);
        l0 = l0 * cor0 + rs0;
        l1 = l1 * cor1 + rs1;

        // ---- O += P V (3-pass split; P frags straight from C-frags) ----
#pragma unroll
        for (int ks = 0; ks < 4; ks++) {
            uint32_t pha[4], pla[4];
            pha[0] = pack_bf2(s[2 * ks][0], s[2 * ks][1]);
            pha[1] = pack_bf2(s[2 * ks][2], s[2 * ks][3]);
            pha[2] = pack_bf2(s[2 * ks + 1][0], s[2 * ks + 1][1]);
            pha[3] = pack_bf2(s[2 * ks + 1][2], s[2 * ks + 1][3]);
            pla[0] = pack_bf2_res(s[2 * ks][0], s[2 * ks][1], pha[0]);
            pla[1] = pack_bf2_res(s[2 * ks][2], s[2 * ks][3], pha[1]);
            pla[2] = pack_bf2_res(s[2 * ks + 1][0], s[2 * ks + 1][1], pha[2]);
            pla[3] = pack_bf2_res(s[2 * ks + 1][2], s[2 * ks + 1][3], pha[3]);
#pragma unroll
            for (int gr = 0; gr < 8; gr++) {
                uint32_t vh4[4], vl4[4];
                uint32_t ro = st + 2 * KVT + (ks * 16 + arow) * ARB +
                              gr * 32 + vcolB;
                ldsm4t(vh4[0], vh4[1], vh4[2], vh4[3], ro);
                ldsm4t(vl4[0], vl4[1], vl4[2], vl4[3], ro + KVT);
                mma_bf16(o[2 * gr], pha, vh4);
                mma_bf16(o[2 * gr], pha, vl4);
                mma_bf16(o[2 * gr], pla, vh4);
                mma_bf16(o[2 * gr + 1], pha, vh4 + 2);
                mma_bf16(o[2 * gr + 1], pha, vl4 + 2);
                mma_bf16(o[2 * gr + 1], pla, vh4 + 2);
            }
        }
        __syncthreads();
        if (t + 2 < NT) load_stage(t & 1, t + 2);
    }

    // ---- epilogue: normalize and write g_A [b][s][h*128+d] ----
    float inv0 = 1.f / l0, inv1 = 1.f / l1;
    const int r0 = qt * 128 + wm + g, r1 = r0 + 8;
#pragma unroll
    for (int j = 0; j < 16; j++) {
        int col = h * 128 + j * 8 + 2 * t4;
        *reinterpret_cast<float2*>(&g_A[((size_t)(b * Sn + r0)) * 4096 + col]) =
            make_float2(o[j][0] * inv0, o[j][1] * inv0);
        *reinterpret_cast<float2*>(&g_A[((size_t)(b * Sn + r1)) * 4096 + col]) =
            make_float2(o[j][2] * inv1, o[j][3] * inv1);
    }
}

// ---------------------------------------------------------------------------
extern "C" void kernel_launch(void* const* d_in, const int* in_sizes, int n_in,
                              void* d_out, int out_size)
{
    const float* hidden = (const float*)d_in[0];
    const float* Wq = (const float*)d_in[2];
    const float* Wk = (const float*)d_in[3];
    const float* Wv = (const float*)d_in[4];
    const float* Wo = (const float*)d_in[5];
    float* out = (float*)d_out;

    float *pQ, *pK, *pV, *pA;
    __nv_bfloat16 *pXh, *pXl, *pQTh, *pQTl, *pKTh, *pKTl, *pVTh, *pVTl, *pOTh, *pOTl;
    __nv_bfloat16 *pQh, *pQl, *pKh, *pKl, *pVh, *pVl;
    cudaGetSymbolAddress((void**)&pQ, g_Q);
    cudaGetSymbolAddress((void**)&pK, g_K);
    cudaGetSymbolAddress((void**)&pV, g_V);
    cudaGetSymbolAddress((void**)&pA, g_A);
    cudaGetSymbolAddress((void**)&pXh, g_Xhi);
    cudaGetSymbolAddress((void**)&pXl, g_Xlo);
    cudaGetSymbolAddress((void**)&pQTh, g_WqThi);
    cudaGetSymbolAddress((void**)&pQTl, g_WqTlo);
    cudaGetSymbolAddress((void**)&pKTh, g_WkThi);
    cudaGetSymbolAddress((void**)&pKTl, g_WkTlo);
    cudaGetSymbolAddress((void**)&pVTh, g_WvThi);
    cudaGetSymbolAddress((void**)&pVTl, g_WvTlo);
    cudaGetSymbolAddress((void**)&pOTh, g_WoThi);
    cudaGetSymbolAddress((void**)&pOTl, g_WoTlo);
    cudaGetSymbolAddress((void**)&pQh, g_Qh);
    cudaGetSymbolAddress((void**)&pQl, g_Ql);
    cudaGetSymbolAddress((void**)&pKh, g_Kh);
    cudaGetSymbolAddress((void**)&pKl, g_Kl);
    cudaGetSymbolAddress((void**)&pVh, g_Vh);
    cudaGetSymbolAddress((void**)&pVl, g_Vl);

    cudaFuncSetAttribute(hgemm_kernel<0>,
                         cudaFuncAttributeMaxDynamicSharedMemorySize, HG_SMEM);
    cudaFuncSetAttribute(hgemm_kernel<1>,
                         cudaFuncAttributeMaxDynamicSharedMemorySize, HG_SMEM);
    cudaFuncSetAttribute(hgemm_kernel<2>,
                         cudaFuncAttributeMaxDynamicSharedMemorySize, HG_SMEM);
    cudaFuncSetAttribute(attn_mma_kernel,
                         cudaFuncAttributeMaxDynamicSharedMemorySize, AT_SMEM);

    // 0) split/transpose conversions
    const int n4x = Mn * Hn / 4;
    split_kernel<<<n4x / 256, 256>>>(hidden, pXh, pXl, n4x);
    dim3 tb(32, 8);
    tsplit_kernel<<<dim3(4096 / 32, 4096 / 32), tb>>>(Wq, pQTh, pQTl, Hn, 4096);
    tsplit_kernel<<<dim3(1024 / 32, 4096 / 32), tb>>>(Wk, pKTh, pKTl, Hn, 1024);
    tsplit_kernel<<<dim3(1024 / 32, 4096 / 32), tb>>>(Wv, pVTh, pVTl, Hn, 1024);
    tsplit_kernel<<<dim3(4096 / 32, 4096 / 32), tb>>>(Wo, pOTh, pOTl, 4096, Hn);

    // 1) projections
    hgemm_kernel<1><<<dim3(4096 / 128, Mn / 128), 256, HG_SMEM>>>(
        pXh, pXl, pQTh, pQTl, pQ, 4096, Hn);
    hgemm_kernel<2><<<dim3(1024 / 128, Mn / 128), 256, HG_SMEM>>>(
        pXh, pXl, pKTh, pKTl, pK, 1024, Hn);
    hgemm_kernel<2><<<dim3(1024 / 128, Mn / 128), 256, HG_SMEM>>>(
        pXh, pXl, pVTh, pVTl, pV, 1024, Hn);

    // 2) RoPE + split (Q gets QK_SCALE folded in); V split
    int totQ = Bn * NHn * Sn * 64;
    int totK = Bn * NKVn * Sn * 64;
    rope_split_kernel<<<totQ / 256, 256>>>(pQ, pQh, pQl, totQ, QK_SCALE);
    rope_split_kernel<<<totK / 256, 256>>>(pK, pKh, pKl, totK, 1.f);
    const int nv4 = Bn * NKVn * Sn * HDn / 4;
    split_kernel<<<nv4 / 256, 256>>>(pV, pVh, pVl, nv4);

    // 3) causal flash attention (bf16 split mma)
    dim3 ga(Sn / 128, NHn, Bn);
    attn_mma_kernel<<<ga, 256, AT_SMEM>>>();

    // 4) output projection
    split_kernel<<<n4x / 256, 256>>>(pA, pXh, pXl, n4x);
    hgemm_kernel<0><<<dim3(4096 / 128, Mn / 128), 256, HG_SMEM>>>(
        pXh, pXl, pOTh, pOTl, out, 4096, Hn);
}